// round 5
// baseline (speedup 1.0000x reference)
#include <cuda_runtime.h>
#include <math.h>
#include <stdint.h>

// ---------------------------------------------------------------------------
// TransformerSelfAttention: B=2, S=2048, D=1024, H=16, HD=64
// GEMMs + attention on mma.sync TF32 (m16n8k8), cp.async double buffering.
// This round: 2 CTA/SM GEMM occupancy + fused QKV GEMM.
// ---------------------------------------------------------------------------

#define D_MODEL 1024
#define SEQ     2048
#define BATCH   2
#define NHEAD   16
#define HDIM    64
#define MROWS   (BATCH * SEQ)        // 4096
#define DFF     (4 * D_MODEL)        // 4096
#define QKVN    (3 * D_MODEL)        // 3072

#define CH      (4u * 1024u * 1024u) // 4M floats chunk
__device__ float g_scratch[96u * 1024u * 1024u];

// ===========================================================================
// helpers
// ===========================================================================
__device__ __forceinline__ uint32_t smem_u32(const void* p) {
    uint32_t a;
    asm("{ .reg .u64 t; cvta.to.shared.u64 t, %1; cvt.u32.u64 %0, t; }"
        : "=r"(a) : "l"(p));
    return a;
}
// unbiased fp32 -> tf32 rounding
__device__ __forceinline__ float tf32r(float x) {
    uint32_t o;
    asm("cvt.rna.tf32.f32 %0, %1;" : "=r"(o) : "f"(x));
    return __uint_as_float(o);
}

#define CP_ASYNC16(dst, src) \
    asm volatile("cp.async.cg.shared.global [%0], [%1], 16;" \
                 :: "r"(dst), "l"(src))
#define CP_COMMIT()  asm volatile("cp.async.commit_group;")
#define CP_WAIT0()   asm volatile("cp.async.wait_group 0;")

__device__ __forceinline__ void mma_tf32(float* c, const uint32_t* a,
                                         const uint32_t* b) {
    asm volatile(
        "mma.sync.aligned.m16n8k8.row.col.f32.tf32.tf32.f32 "
        "{%0,%1,%2,%3}, {%4,%5,%6,%7}, {%8,%9}, {%0,%1,%2,%3};"
        : "+f"(c[0]), "+f"(c[1]), "+f"(c[2]), "+f"(c[3])
        : "r"(a[0]), "r"(a[1]), "r"(a[2]), "r"(a[3]), "r"(b[0]), "r"(b[1]));
}

// ===========================================================================
// LayerNorm
// ===========================================================================
__global__ void ln_kernel(const float* __restrict__ x,
                          const float* __restrict__ g,
                          const float* __restrict__ b,
                          float* __restrict__ out,
                          float* __restrict__ outr) {
    __shared__ float red[256], red2[256];
    __shared__ float s_mu, s_rstd;
    const int row = blockIdx.x;
    const int tid = threadIdx.x;
    const float* xr = x + (size_t)row * D_MODEL;

    float vals[4];
    float s = 0.f, s2 = 0.f;
#pragma unroll
    for (int i = 0; i < 4; i++) {
        float v = xr[tid + i * 256];
        vals[i] = v;
        s += v; s2 += v * v;
    }
    red[tid] = s; red2[tid] = s2;
    __syncthreads();
    for (int off = 128; off > 0; off >>= 1) {
        if (tid < off) { red[tid] += red[tid + off]; red2[tid] += red2[tid + off]; }
        __syncthreads();
    }
    if (tid == 0) {
        float mu = red[0] * (1.0f / D_MODEL);
        float var = red2[0] * (1.0f / D_MODEL) - mu * mu;
        s_mu = mu;
        s_rstd = rsqrtf(var + 1e-5f);
    }
    __syncthreads();
    const float mu = s_mu, rstd = s_rstd;
#pragma unroll
    for (int i = 0; i < 4; i++) {
        int c = tid + i * 256;
        float v = (vals[i] - mu) * rstd * g[c] + b[c];
        if (out)  out[(size_t)row * D_MODEL + c] = v;
        if (outr) outr[(size_t)row * D_MODEL + c] = tf32r(v);
    }
}

// ===========================================================================
// Transpose + tf32 round
// ===========================================================================
__global__ void transpose_kernel(const float* __restrict__ in,
                                 float* __restrict__ out, int R, int C) {
    __shared__ float t[32][33];
    const int bx = blockIdx.x * 32, by = blockIdx.y * 32;
    const int tx = threadIdx.x, ty = threadIdx.y;
#pragma unroll
    for (int j = 0; j < 32; j += 8)
        t[ty + j][tx] = in[(size_t)(by + ty + j) * C + bx + tx];
    __syncthreads();
#pragma unroll
    for (int j = 0; j < 32; j += 8)
        out[(size_t)(bx + ty + j) * R + by + tx] = tf32r(t[tx][ty + j]);
}

// ===========================================================================
// TF32 mma.sync GEMM, 128x128 CTA tile, BK=32, 8 warps, 2 CTA/SM.
// ===========================================================================
#define LDSA 36
#define TILE_F (128 * LDSA)
#define STAGE_F (2 * TILE_F)
#define GEMM_SMEM (2 * STAGE_F * 4)

__device__ __forceinline__ void tile_load(const float* __restrict__ Ag,
                                          const float* __restrict__ Bg,
                                          int K, int it, uint32_t sbu, int tid) {
    const uint32_t dst = sbu + (uint32_t)(it & 1) * (STAGE_F * 4);
#pragma unroll
    for (int j = 0; j < 4; j++) {
        const int idx = tid + j * 256;
        const int row = idx >> 3;
        const int c8 = idx & 7;
        const uint32_t so = (uint32_t)(row * LDSA + c8 * 4) * 4u;
        const float* ga = Ag + (size_t)row * K + it * 32 + c8 * 4;
        const float* gb = Bg + (size_t)row * K + it * 32 + c8 * 4;
        CP_ASYNC16(dst + so, ga);
        CP_ASYNC16(dst + TILE_F * 4 + so, gb);
    }
    CP_COMMIT();
}

template <bool GELU>
__global__ __launch_bounds__(256, 2)
void tgemm(const float* __restrict__ A, const float* __restrict__ Bt,
           float* __restrict__ C, int M, int N, int K,
           const float* __restrict__ bias, const float* __restrict__ residual) {
    extern __shared__ float sm[];
    const uint32_t sbu = smem_u32(sm);

    const int tid = threadIdx.x;
    const int w = tid >> 5, lane = tid & 31;
    const int g = lane >> 2, t = lane & 3;
    const int wm = w & 1, wn = w >> 1;
    const int m0 = blockIdx.y * 128, n0 = blockIdx.x * 128;
    const float* Ag = A + (size_t)m0 * K;
    const float* Bg = Bt + (size_t)n0 * K;
    const int nk = K >> 5;

    float c[4][4][4];
#pragma unroll
    for (int i = 0; i < 4; i++)
#pragma unroll
        for (int j = 0; j < 4; j++)
#pragma unroll
            for (int q = 0; q < 4; q++) c[i][j][q] = 0.f;

    tile_load(Ag, Bg, K, 0, sbu, tid);

    for (int it = 0; it < nk; it++) {
        CP_WAIT0();
        __syncthreads();
        if (it + 1 < nk) tile_load(Ag, Bg, K, it + 1, sbu, tid);

        const float* a = sm + (it & 1) * STAGE_F;
        const float* b = a + TILE_F;
#pragma unroll
        for (int ks = 0; ks < 4; ks++) {
            const int k0 = ks * 8;
            uint32_t ar[4][4];
#pragma unroll
            for (int mf = 0; mf < 4; mf++) {
                const float* ap = a + (wm * 64 + mf * 16 + g) * LDSA + k0 + t;
                ar[mf][0] = __float_as_uint(ap[0]);
                ar[mf][1] = __float_as_uint(ap[8 * LDSA]);
                ar[mf][2] = __float_as_uint(ap[4]);
                ar[mf][3] = __float_as_uint(ap[8 * LDSA + 4]);
            }
            uint32_t br[4][2];
#pragma unroll
            for (int nf = 0; nf < 4; nf++) {
                const float* bp = b + (wn * 32 + nf * 8 + g) * LDSA + k0 + t;
                br[nf][0] = __float_as_uint(bp[0]);
                br[nf][1] = __float_as_uint(bp[4]);
            }
#pragma unroll
            for (int mf = 0; mf < 4; mf++)
#pragma unroll
                for (int nf = 0; nf < 4; nf++)
                    mma_tf32(c[mf][nf], ar[mf], br[nf]);
        }
        __syncthreads();
    }

#pragma unroll
    for (int mf = 0; mf < 4; mf++) {
        const int r0 = m0 + wm * 64 + mf * 16 + g;
#pragma unroll
        for (int half = 0; half < 2; half++) {
            const int row = r0 + half * 8;
            float* crow = C + (size_t)row * N;
            const float* rrow = residual ? residual + (size_t)row * N : nullptr;
#pragma unroll
            for (int nf = 0; nf < 4; nf++) {
                const int col = n0 + wn * 32 + nf * 8 + t * 2;
                float v0 = c[mf][nf][half * 2 + 0];
                float v1 = c[mf][nf][half * 2 + 1];
                if (bias) { v0 += bias[col]; v1 += bias[col + 1]; }
                if (GELU) {
                    v0 = 0.5f * v0 * (1.0f + erff(v0 * 0.70710678118654752f));
                    v1 = 0.5f * v1 * (1.0f + erff(v1 * 0.70710678118654752f));
                    v0 = tf32r(v0); v1 = tf32r(v1);
                }
                if (rrow) { v0 += rrow[col]; v1 += rrow[col + 1]; }
                float2 o; o.x = v0; o.y = v1;
                *(float2*)(crow + col) = o;
            }
        }
    }
    (void)M;
}

// ===========================================================================
// Flash attention on mma.sync TF32, reading packed qkv [MROWS, 3072].
// Per CTA: one (b,h), 64 q-rows, 4 warps (each m16 x n64 fragments).
// ===========================================================================
#define ALD 68
#define ATT_SMEM ((4 * 64 * ALD + 3 * 64) * 4)
#define QS QKVN   // row stride of packed qkv

__global__ __launch_bounds__(128)
void attn_kernel(const float* __restrict__ qkv, float* __restrict__ y) {
    extern __shared__ float sm[];
    float* sQ  = sm;
    float* sK  = sQ  + 64 * ALD;
    float* sVt = sK  + 64 * ALD;
    float* sP  = sVt + 64 * ALD;
    float* sM  = sP  + 64 * ALD;
    float* sL  = sM + 64;
    float* sA  = sL + 64;

    const int tid  = threadIdx.x;
    const int wid  = tid >> 5;
    const int lane = tid & 31;
    const int g = lane >> 2, t = lane & 3;
    const int wm0 = wid * 16;

    const int bh = blockIdx.x;
    const int b  = bh >> 4;
    const int h  = bh & 15;
    const int q0 = blockIdx.y * 64;

    const size_t baseq = (size_t)b * SEQ * QS + (size_t)h * HDIM;
    const float* qg = qkv + baseq;
    const float* kg = qkv + baseq + D_MODEL;
    const float* vg = qkv + baseq + 2 * D_MODEL;

#pragma unroll
    for (int j = 0; j < 8; j++) {
        const int idx = tid + j * 128;
        const int r = idx >> 4, c4 = (idx & 15) << 2;
        float4 tq = *(const float4*)(qg + (size_t)(q0 + r) * QS + c4);
        float* d = &sQ[r * ALD + c4];
        d[0] = tf32r(tq.x); d[1] = tf32r(tq.y);
        d[2] = tf32r(tq.z); d[3] = tf32r(tq.w);
    }
    if (tid < 64) { sM[tid] = -INFINITY; sL[tid] = 0.f; }

    float o[8][4];
#pragma unroll
    for (int i = 0; i < 8; i++)
#pragma unroll
        for (int j = 0; j < 4; j++) o[i][j] = 0.f;

    __syncthreads();

    for (int kt = 0; kt < SEQ / 64; kt++) {
        const int k0 = kt * 64;
#pragma unroll
        for (int j = 0; j < 8; j++) {
            const int idx = tid + j * 128;
            const int r = idx >> 4, c4 = (idx & 15) << 2;
            float4 tk = *(const float4*)(kg + (size_t)(k0 + r) * QS + c4);
            float* dk = &sK[r * ALD + c4];
            dk[0] = tf32r(tk.x); dk[1] = tf32r(tk.y);
            dk[2] = tf32r(tk.z); dk[3] = tf32r(tk.w);
            float4 tv = *(const float4*)(vg + (size_t)(k0 + r) * QS + c4);
            sVt[(c4 + 0) * ALD + r] = tf32r(tv.x);
            sVt[(c4 + 1) * ALD + r] = tf32r(tv.y);
            sVt[(c4 + 2) * ALD + r] = tf32r(tv.z);
            sVt[(c4 + 3) * ALD + r] = tf32r(tv.w);
        }
        __syncthreads();

        float sacc[8][4];
#pragma unroll
        for (int i = 0; i < 8; i++)
#pragma unroll
            for (int j = 0; j < 4; j++) sacc[i][j] = 0.f;
#pragma unroll
        for (int ks = 0; ks < 8; ks++) {
            const int kk = ks * 8;
            uint32_t a[4];
            const float* ap = sQ + (wm0 + g) * ALD + kk + t;
            a[0] = __float_as_uint(ap[0]);
            a[1] = __float_as_uint(ap[8 * ALD]);
            a[2] = __float_as_uint(ap[4]);
            a[3] = __float_as_uint(ap[8 * ALD + 4]);
#pragma unroll
            for (int nf = 0; nf < 8; nf++) {
                uint32_t bb[2];
                const float* bp = sK + (nf * 8 + g) * ALD + kk + t;
                bb[0] = __float_as_uint(bp[0]);
                bb[1] = __float_as_uint(bp[4]);
                mma_tf32(sacc[nf], a, bb);
            }
        }

        const float scale = 0.125f;
#pragma unroll
        for (int nf = 0; nf < 8; nf++) {
            const int col = nf * 8 + t * 2;
#pragma unroll
            for (int half = 0; half < 2; half++) {
                const int r = wm0 + g + half * 8;
                float v0 = sacc[nf][half * 2 + 0] * scale;
                float v1 = sacc[nf][half * 2 + 1] * scale;
                if (q0 + r == k0 + col)     v0 = -INFINITY;
                if (q0 + r == k0 + col + 1) v1 = -INFINITY;
                float2 pv; pv.x = v0; pv.y = v1;
                *(float2*)(sP + r * ALD + col) = pv;
            }
        }
        __syncthreads();

        {
            const int r = tid >> 1, hf = tid & 1;
            float* row = sP + r * ALD + hf * 32;
            float mt = -INFINITY;
#pragma unroll 8
            for (int c = 0; c < 32; c++) mt = fmaxf(mt, row[c]);
            mt = fmaxf(mt, __shfl_xor_sync(0xffffffffu, mt, 1));
            const float mold = sM[r];
            const float mnew = fmaxf(mold, mt);
            float ps = 0.f;
#pragma unroll 8
            for (int c = 0; c < 32; c++) {
                float p = __expf(row[c] - mnew);
                row[c] = tf32r(p);
                ps += p;
            }
            ps += __shfl_xor_sync(0xffffffffu, ps, 1);
            if (hf == 0) {
                const float alpha = __expf(mold - mnew);
                sL[r] = sL[r] * alpha + ps;
                sM[r] = mnew;
                sA[r] = alpha;
            }
        }
        __syncthreads();

        const float al0 = sA[wm0 + g];
        const float al1 = sA[wm0 + g + 8];
#pragma unroll
        for (int nf = 0; nf < 8; nf++) {
            o[nf][0] *= al0; o[nf][1] *= al0;
            o[nf][2] *= al1; o[nf][3] *= al1;
        }
#pragma unroll
        for (int ks = 0; ks < 8; ks++) {
            const int kk = ks * 8;
            uint32_t a[4];
            const float* ap = sP + (wm0 + g) * ALD + kk + t;
            a[0] = __float_as_uint(ap[0]);
            a[1] = __float_as_uint(ap[8 * ALD]);
            a[2] = __float_as_uint(ap[4]);
            a[3] = __float_as_uint(ap[8 * ALD + 4]);
#pragma unroll
            for (int nf = 0; nf < 8; nf++) {
                uint32_t bb[2];
                const float* bp = sVt + (nf * 8 + g) * ALD + kk + t;
                bb[0] = __float_as_uint(bp[0]);
                bb[1] = __float_as_uint(bp[4]);
                mma_tf32(o[nf], a, bb);
            }
        }
        __syncthreads();
    }

    const float il0 = 1.0f / sL[wm0 + g];
    const float il1 = 1.0f / sL[wm0 + g + 8];
    float* yg = y + (size_t)b * SEQ * D_MODEL + (size_t)h * HDIM;
#pragma unroll
    for (int nf = 0; nf < 8; nf++) {
        const int col = nf * 8 + t * 2;
        const int r0 = q0 + wm0 + g;
        float2 o0; o0.x = tf32r(o[nf][0] * il0); o0.y = tf32r(o[nf][1] * il0);
        *(float2*)(yg + (size_t)r0 * D_MODEL + col) = o0;
        float2 o1; o1.x = tf32r(o[nf][2] * il1); o1.y = tf32r(o[nf][3] * il1);
        *(float2*)(yg + (size_t)(r0 + 8) * D_MODEL + col) = o1;
    }
}

// ===========================================================================
// launch
// ===========================================================================
extern "C" void kernel_launch(void* const* d_in, const int* in_sizes, int n_in,
                              void* d_out, int out_size) {
    const float* x   = (const float*)d_in[0];
    const float* Wk  = (const float*)d_in[1];
    const float* Wq  = (const float*)d_in[2];
    const float* Wv  = (const float*)d_in[3];
    const float* Wp  = (const float*)d_in[4];
    const float* bp  = (const float*)d_in[5];
    const float* g1  = (const float*)d_in[6];
    const float* b1  = (const float*)d_in[7];
    const float* g2  = (const float*)d_in[8];
    const float* b2  = (const float*)d_in[9];
    const float* W1  = (const float*)d_in[10];
    const float* bm1 = (const float*)d_in[11];
    const float* W2  = (const float*)d_in[12];
    const float* bm2 = (const float*)d_in[13];
    float* out = (float*)d_out;

    float* S = nullptr;
    cudaGetSymbolAddress((void**)&S, g_scratch);
    float* xn    = S + 0 * CH;
    float* xnr   = S + 1 * CH;
    float* qkv   = S + 2 * CH;   // 12M floats (chunks 2,3,4)
    float* yb    = S + 5 * CH;
    float* hb    = S + 6 * CH;
    float* hn    = S + 7 * CH;
    float* m1    = S + 8 * CH;   // 16M floats (8..11)
    float* WqkvT = S + 12 * CH;  // 12M floats [3072,1024] (12,13,14)
    float* WpT   = S + 15 * CH;
    float* W1T   = S + 16 * CH;  // 4M (16..19)
    float* W2T   = S + 20 * CH;  // 4M (20..23)

    cudaFuncSetAttribute(attn_kernel, cudaFuncAttributeMaxDynamicSharedMemorySize,
                         ATT_SMEM);
    cudaFuncSetAttribute(tgemm<false>, cudaFuncAttributeMaxDynamicSharedMemorySize,
                         GEMM_SMEM);
    cudaFuncSetAttribute(tgemm<true>, cudaFuncAttributeMaxDynamicSharedMemorySize,
                         GEMM_SMEM);

    // 0) transpose weights -> [N,K], tf32-rounded; QKV packed into one B
    dim3 tb(32, 8);
    dim3 tg(D_MODEL / 32, D_MODEL / 32);
    transpose_kernel<<<tg, tb>>>(Wq, WqkvT + 0 * D_MODEL * D_MODEL, D_MODEL, D_MODEL);
    transpose_kernel<<<tg, tb>>>(Wk, WqkvT + 1 * D_MODEL * D_MODEL, D_MODEL, D_MODEL);
    transpose_kernel<<<tg, tb>>>(Wv, WqkvT + 2 * D_MODEL * D_MODEL, D_MODEL, D_MODEL);
    transpose_kernel<<<tg, tb>>>(Wp, WpT, D_MODEL, D_MODEL);
    transpose_kernel<<<dim3(DFF/32, D_MODEL/32), tb>>>(W1, W1T, D_MODEL, DFF);
    transpose_kernel<<<dim3(D_MODEL/32, DFF/32), tb>>>(W2, W2T, DFF, D_MODEL);

    // 1) xn = LN1(x): exact (residual) + rounded (GEMM A)
    ln_kernel<<<MROWS, 256>>>(x, g1, b1, xn, xnr);

    // 2) qkv = xnr @ Wqkv  (single fused GEMM, N=3072)
    dim3 gqkv(QKVN / 128, MROWS / 128);
    tgemm<false><<<gqkv, 256, GEMM_SMEM>>>(xnr, WqkvT, qkv, MROWS, QKVN, D_MODEL, nullptr, nullptr);

    // 3) flash attention (tensorized) -> yb
    dim3 ag(BATCH * NHEAD, SEQ / 64);
    attn_kernel<<<ag, 128, ATT_SMEM>>>(qkv, yb);

    // 4) h = xn + yb @ Wp + bp
    dim3 g1024(D_MODEL / 128, MROWS / 128);
    tgemm<false><<<g1024, 256, GEMM_SMEM>>>(yb, WpT, hb, MROWS, D_MODEL, D_MODEL, bp, xn);

    // 5) hn = LN2(h), rounded only (GEMM input)
    ln_kernel<<<MROWS, 256>>>(hb, g2, b2, nullptr, hn);

    // 6) m1 = tf32(gelu(hn @ W1 + bm1))
    dim3 g4096(DFF / 128, MROWS / 128);
    tgemm<true><<<g4096, 256, GEMM_SMEM>>>(hn, W1T, m1, MROWS, DFF, D_MODEL, bm1, nullptr);

    // 7) out = hb + m1 @ W2 + bm2
    tgemm<false><<<g1024, 256, GEMM_SMEM>>>(m1, W2T, out, MROWS, D_MODEL, DFF, bm2, hb);

    (void)in_sizes; (void)n_in; (void)out_size;
}

// round 6
// speedup vs baseline: 1.3286x; 1.3286x over previous
#include <cuda_runtime.h>
#include <cuda_fp16.h>
#include <math.h>
#include <stdint.h>

// ---------------------------------------------------------------------------
// TransformerSelfAttention: B=2, S=2048, D=1024, H=16, HD=64
// GEMMs + attention on mma.sync FP16 (m16n8k16, fp32 accum).
// fp16 rne has the same 10-bit-mantissa error as tf32 but 2x tensor rate.
// ---------------------------------------------------------------------------

#define D_MODEL 1024
#define SEQ     2048
#define BATCH   2
#define NHEAD   16
#define HDIM    64
#define MROWS   (BATCH * SEQ)        // 4096
#define DFF     (4 * D_MODEL)        // 4096
#define QKVN    (3 * D_MODEL)        // 3072

#define CH      (4u * 1024u * 1024u) // 4M floats chunk
__device__ float g_scratch[56u * 1024u * 1024u];

// ===========================================================================
// helpers
// ===========================================================================
__device__ __forceinline__ uint32_t smem_u32(const void* p) {
    uint32_t a;
    asm("{ .reg .u64 t; cvta.to.shared.u64 t, %1; cvt.u32.u64 %0, t; }"
        : "=r"(a) : "l"(p));
    return a;
}

#define CP_ASYNC16(dst, src) \
    asm volatile("cp.async.cg.shared.global [%0], [%1], 16;" \
                 :: "r"(dst), "l"(src))
#define CP_COMMIT()  asm volatile("cp.async.commit_group;")
#define CP_WAIT0()   asm volatile("cp.async.wait_group 0;")

// m16n8k16 fp16 MMA, fp32 accumulate
__device__ __forceinline__ void mma_f16(float* c, const uint32_t* a,
                                        const uint32_t* b) {
    asm volatile(
        "mma.sync.aligned.m16n8k16.row.col.f32.f16.f16.f32 "
        "{%0,%1,%2,%3}, {%4,%5,%6,%7}, {%8,%9}, {%0,%1,%2,%3};"
        : "+f"(c[0]), "+f"(c[1]), "+f"(c[2]), "+f"(c[3])
        : "r"(a[0]), "r"(a[1]), "r"(a[2]), "r"(a[3]), "r"(b[0]), "r"(b[1]));
}

// ===========================================================================
// LayerNorm: fp32 out (residual) + fp16 out (GEMM operand)
// ===========================================================================
__global__ void ln_kernel(const float* __restrict__ x,
                          const float* __restrict__ g,
                          const float* __restrict__ b,
                          float* __restrict__ out,
                          __half* __restrict__ outh) {
    __shared__ float red[256], red2[256];
    __shared__ float s_mu, s_rstd;
    const int row = blockIdx.x;
    const int tid = threadIdx.x;
    const float* xr = x + (size_t)row * D_MODEL;

    float vals[4];
    float s = 0.f, s2 = 0.f;
#pragma unroll
    for (int i = 0; i < 4; i++) {
        float v = xr[tid + i * 256];
        vals[i] = v;
        s += v; s2 += v * v;
    }
    red[tid] = s; red2[tid] = s2;
    __syncthreads();
    for (int off = 128; off > 0; off >>= 1) {
        if (tid < off) { red[tid] += red[tid + off]; red2[tid] += red2[tid + off]; }
        __syncthreads();
    }
    if (tid == 0) {
        float mu = red[0] * (1.0f / D_MODEL);
        float var = red2[0] * (1.0f / D_MODEL) - mu * mu;
        s_mu = mu;
        s_rstd = rsqrtf(var + 1e-5f);
    }
    __syncthreads();
    const float mu = s_mu, rstd = s_rstd;
#pragma unroll
    for (int i = 0; i < 4; i++) {
        int c = tid + i * 256;
        float v = (vals[i] - mu) * rstd * g[c] + b[c];
        if (out)  out[(size_t)row * D_MODEL + c] = v;
        if (outh) outh[(size_t)row * D_MODEL + c] = __float2half_rn(v);
    }
}

// ===========================================================================
// Transpose: half out[C,R] = rne(in[R,C]^T)
// ===========================================================================
__global__ void transpose_kernel(const float* __restrict__ in,
                                 __half* __restrict__ out, int R, int C) {
    __shared__ float t[32][33];
    const int bx = blockIdx.x * 32, by = blockIdx.y * 32;
    const int tx = threadIdx.x, ty = threadIdx.y;
#pragma unroll
    for (int j = 0; j < 32; j += 8)
        t[ty + j][tx] = in[(size_t)(by + ty + j) * C + bx + tx];
    __syncthreads();
#pragma unroll
    for (int j = 0; j < 32; j += 8)
        out[(size_t)(bx + ty + j) * R + by + tx] = __float2half_rn(t[tx][ty + j]);
}

// ===========================================================================
// FP16 mma.sync GEMM: C = A[M,K] @ Bt[N,K]^T (+bias)(gelu)(+residual)
// 128x128 CTA tile, BK=32, 8 warps (2Mx4N, 64x32 warp tile), double buffer.
// Outputs: Cf (fp32) and/or Chh (fp16), selectable.
// ===========================================================================
#define LDH 40                         // halves per SMEM row (32 data + 8 pad)
#define TILE_H (128 * LDH)             // halves per tile
#define STAGE_B (2 * TILE_H * 2)       // bytes per stage (A+B)  = 20480
#define GEMM_SMEM (2 * STAGE_B)        // 40960 bytes

__device__ __forceinline__ void tile_load_h(const __half* __restrict__ Ag,
                                            const __half* __restrict__ Bg,
                                            int K, int it, uint32_t sbu, int tid) {
    const uint32_t dst = sbu + (uint32_t)(it & 1) * STAGE_B;
#pragma unroll
    for (int j = 0; j < 2; j++) {
        const int idx = tid + j * 256;           // 0..511
        const int row = idx >> 2;
        const int c = idx & 3;                   // 16B chunk (8 halves)
        const uint32_t so = (uint32_t)(row * LDH * 2 + c * 16);
        const __half* ga = Ag + (size_t)row * K + it * 32 + c * 8;
        const __half* gb = Bg + (size_t)row * K + it * 32 + c * 8;
        CP_ASYNC16(dst + so, ga);
        CP_ASYNC16(dst + TILE_H * 2 + so, gb);
    }
    CP_COMMIT();
}

template <bool GELU>
__global__ __launch_bounds__(256, 2)
void tgemm(const __half* __restrict__ A, const __half* __restrict__ Bt,
           float* __restrict__ Cf, __half* __restrict__ Chh,
           int M, int N, int K,
           const float* __restrict__ bias, const float* __restrict__ residual) {
    extern __shared__ char smraw[];
    __half* sh = (__half*)smraw;
    const uint32_t sbu = smem_u32(smraw);

    const int tid = threadIdx.x;
    const int w = tid >> 5, lane = tid & 31;
    const int g = lane >> 2, t = lane & 3;
    const int wm = w & 1, wn = w >> 1;
    const int m0 = blockIdx.y * 128, n0 = blockIdx.x * 128;
    const __half* Ag = A + (size_t)m0 * K;
    const __half* Bg = Bt + (size_t)n0 * K;
    const int nk = K >> 5;

    float c[4][4][4];
#pragma unroll
    for (int i = 0; i < 4; i++)
#pragma unroll
        for (int j = 0; j < 4; j++)
#pragma unroll
            for (int q = 0; q < 4; q++) c[i][j][q] = 0.f;

    tile_load_h(Ag, Bg, K, 0, sbu, tid);

    for (int it = 0; it < nk; it++) {
        CP_WAIT0();
        __syncthreads();
        if (it + 1 < nk) tile_load_h(Ag, Bg, K, it + 1, sbu, tid);

        const __half* a = sh + (size_t)(it & 1) * (STAGE_B / 2);
        const __half* b = a + TILE_H;
#pragma unroll
        for (int ks = 0; ks < 2; ks++) {            // 2 x k16
            const int kk = ks * 16;
            uint32_t ar[4][4];
#pragma unroll
            for (int mf = 0; mf < 4; mf++) {
                const __half* ap = a + (wm * 64 + mf * 16 + g) * LDH + kk + 2 * t;
                ar[mf][0] = *(const uint32_t*)(ap);
                ar[mf][1] = *(const uint32_t*)(ap + 8 * LDH);
                ar[mf][2] = *(const uint32_t*)(ap + 8);
                ar[mf][3] = *(const uint32_t*)(ap + 8 * LDH + 8);
            }
            uint32_t br[4][2];
#pragma unroll
            for (int nf = 0; nf < 4; nf++) {
                const __half* bp = b + (wn * 32 + nf * 8 + g) * LDH + kk + 2 * t;
                br[nf][0] = *(const uint32_t*)(bp);
                br[nf][1] = *(const uint32_t*)(bp + 8);
            }
#pragma unroll
            for (int mf = 0; mf < 4; mf++)
#pragma unroll
                for (int nf = 0; nf < 4; nf++)
                    mma_f16(c[mf][nf], ar[mf], br[nf]);
        }
        __syncthreads();
    }

#pragma unroll
    for (int mf = 0; mf < 4; mf++) {
        const int r0 = m0 + wm * 64 + mf * 16 + g;
#pragma unroll
        for (int half = 0; half < 2; half++) {
            const int row = r0 + half * 8;
            const float* rrow = residual ? residual + (size_t)row * N : nullptr;
#pragma unroll
            for (int nf = 0; nf < 4; nf++) {
                const int col = n0 + wn * 32 + nf * 8 + t * 2;
                float v0 = c[mf][nf][half * 2 + 0];
                float v1 = c[mf][nf][half * 2 + 1];
                if (bias) { v0 += bias[col]; v1 += bias[col + 1]; }
                if (GELU) {
                    v0 = 0.5f * v0 * (1.0f + erff(v0 * 0.70710678118654752f));
                    v1 = 0.5f * v1 * (1.0f + erff(v1 * 0.70710678118654752f));
                }
                if (rrow) { v0 += rrow[col]; v1 += rrow[col + 1]; }
                if (Cf) {
                    float2 o; o.x = v0; o.y = v1;
                    *(float2*)(Cf + (size_t)row * N + col) = o;
                }
                if (Chh) {
                    __half2 oh;
                    oh.x = __float2half_rn(v0); oh.y = __float2half_rn(v1);
                    *(__half2*)(Chh + (size_t)row * N + col) = oh;
                }
            }
        }
    }
    (void)M;
}

// ===========================================================================
// Flash attention on fp16 mma. qkv packed [MROWS, 3072] half.
// Per CTA: one (b,h), 64 q-rows, 4 warps. Output y fp16.
// ===========================================================================
#define LQH 72     // halves per SMEM row (64 data + 8 pad)
#define SLD 68     // fp32 score row stride
// byte layout: sQ, sK, sVt, sP (half, 64*LQH each), sS (fp32 64*SLD), stats
#define SQ_OFF   0
#define SK_OFF   (SQ_OFF + 64 * LQH * 2)
#define SVT_OFF  (SK_OFF + 64 * LQH * 2)
#define SP_OFF   (SVT_OFF + 64 * LQH * 2)
#define SS_OFF   (SP_OFF + 64 * LQH * 2)
#define STAT_OFF (SS_OFF + 64 * SLD * 4)
#define ATT_SMEM (STAT_OFF + 3 * 64 * 4)
#define QS QKVN

__global__ __launch_bounds__(128)
void attn_kernel(const __half* __restrict__ qkv, __half* __restrict__ y) {
    extern __shared__ char smraw[];
    __half* sQ  = (__half*)(smraw + SQ_OFF);
    __half* sK  = (__half*)(smraw + SK_OFF);
    __half* sVt = (__half*)(smraw + SVT_OFF);
    __half* sP  = (__half*)(smraw + SP_OFF);
    float*  sS  = (float*)(smraw + SS_OFF);
    float*  sM  = (float*)(smraw + STAT_OFF);
    float*  sL  = sM + 64;
    float*  sA  = sL + 64;

    const int tid  = threadIdx.x;
    const int wid  = tid >> 5;
    const int lane = tid & 31;
    const int g = lane >> 2, t = lane & 3;
    const int wm0 = wid * 16;

    const int bh = blockIdx.x;
    const int b  = bh >> 4;
    const int h  = bh & 15;
    const int q0 = blockIdx.y * 64;

    const size_t baseq = (size_t)b * SEQ * QS + (size_t)h * HDIM;
    const __half* qg = qkv + baseq;
    const __half* kg = qkv + baseq + D_MODEL;
    const __half* vg = qkv + baseq + 2 * D_MODEL;

    // load Q tile (64 x 64 halves)
#pragma unroll
    for (int j = 0; j < 4; j++) {
        const int idx = tid + j * 128;          // 0..511
        const int r = idx >> 3, c = idx & 7;    // 16B chunks
        uint4 tq = *(const uint4*)(qg + (size_t)(q0 + r) * QS + c * 8);
        *(uint4*)(sQ + r * LQH + c * 8) = tq;
    }
    if (tid < 64) { sM[tid] = -INFINITY; sL[tid] = 0.f; }

    float o[8][4];
#pragma unroll
    for (int i = 0; i < 8; i++)
#pragma unroll
        for (int j = 0; j < 4; j++) o[i][j] = 0.f;

    __syncthreads();

    for (int kt = 0; kt < SEQ / 64; kt++) {
        const int k0 = kt * 64;
        // load K tile; V transposed
#pragma unroll
        for (int j = 0; j < 4; j++) {
            const int idx = tid + j * 128;
            const int r = idx >> 3, c = idx & 7;
            uint4 tk = *(const uint4*)(kg + (size_t)(k0 + r) * QS + c * 8);
            *(uint4*)(sK + r * LQH + c * 8) = tk;
            uint4 tv = *(const uint4*)(vg + (size_t)(k0 + r) * QS + c * 8);
            const __half* hv = (const __half*)&tv;
#pragma unroll
            for (int q = 0; q < 8; q++)
                sVt[(c * 8 + q) * LQH + r] = hv[q];
        }
        __syncthreads();

        // S = Q @ K^T  (m16 x n64, k=64)
        float sacc[8][4];
#pragma unroll
        for (int i = 0; i < 8; i++)
#pragma unroll
            for (int j = 0; j < 4; j++) sacc[i][j] = 0.f;
#pragma unroll
        for (int ks = 0; ks < 4; ks++) {
            const int kk = ks * 16;
            uint32_t a[4];
            const __half* ap = sQ + (wm0 + g) * LQH + kk + 2 * t;
            a[0] = *(const uint32_t*)(ap);
            a[1] = *(const uint32_t*)(ap + 8 * LQH);
            a[2] = *(const uint32_t*)(ap + 8);
            a[3] = *(const uint32_t*)(ap + 8 * LQH + 8);
#pragma unroll
            for (int nf = 0; nf < 8; nf++) {
                uint32_t bb[2];
                const __half* bp = sK + (nf * 8 + g) * LQH + kk + 2 * t;
                bb[0] = *(const uint32_t*)(bp);
                bb[1] = *(const uint32_t*)(bp + 8);
                mma_f16(sacc[nf], a, bb);
            }
        }

        // scale + diag mask -> sS (fp32)
        const float scale = 0.125f;
#pragma unroll
        for (int nf = 0; nf < 8; nf++) {
            const int col = nf * 8 + t * 2;
#pragma unroll
            for (int half = 0; half < 2; half++) {
                const int r = wm0 + g + half * 8;
                float v0 = sacc[nf][half * 2 + 0] * scale;
                float v1 = sacc[nf][half * 2 + 1] * scale;
                if (q0 + r == k0 + col)     v0 = -INFINITY;
                if (q0 + r == k0 + col + 1) v1 = -INFINITY;
                float2 pv; pv.x = v0; pv.y = v1;
                *(float2*)(sS + r * SLD + col) = pv;
            }
        }
        __syncthreads();

        // online softmax: 2 threads/row, write P as fp16
        {
            const int r = tid >> 1, hf = tid & 1;
            const float* row = sS + r * SLD + hf * 32;
            __half* prow = sP + r * LQH + hf * 32;
            float mt = -INFINITY;
#pragma unroll 8
            for (int c = 0; c < 32; c++) mt = fmaxf(mt, row[c]);
            mt = fmaxf(mt, __shfl_xor_sync(0xffffffffu, mt, 1));
            const float mold = sM[r];
            const float mnew = fmaxf(mold, mt);
            float ps = 0.f;
#pragma unroll 8
            for (int c = 0; c < 32; c++) {
                float p = __expf(row[c] - mnew);
                prow[c] = __float2half_rn(p);
                ps += p;
            }
            ps += __shfl_xor_sync(0xffffffffu, ps, 1);
            if (hf == 0) {
                const float alpha = __expf(mold - mnew);
                sL[r] = sL[r] * alpha + ps;
                sM[r] = mnew;
                sA[r] = alpha;
            }
        }
        __syncthreads();

        // O = O*alpha + P @ V
        const float al0 = sA[wm0 + g];
        const float al1 = sA[wm0 + g + 8];
#pragma unroll
        for (int nf = 0; nf < 8; nf++) {
            o[nf][0] *= al0; o[nf][1] *= al0;
            o[nf][2] *= al1; o[nf][3] *= al1;
        }
#pragma unroll
        for (int ks = 0; ks < 4; ks++) {
            const int kk = ks * 16;
            uint32_t a[4];
            const __half* ap = sP + (wm0 + g) * LQH + kk + 2 * t;
            a[0] = *(const uint32_t*)(ap);
            a[1] = *(const uint32_t*)(ap + 8 * LQH);
            a[2] = *(const uint32_t*)(ap + 8);
            a[3] = *(const uint32_t*)(ap + 8 * LQH + 8);
#pragma unroll
            for (int nf = 0; nf < 8; nf++) {
                uint32_t bb[2];
                const __half* bp = sVt + (nf * 8 + g) * LQH + kk + 2 * t;
                bb[0] = *(const uint32_t*)(bp);
                bb[1] = *(const uint32_t*)(bp + 8);
                mma_f16(o[nf], a, bb);
            }
        }
        __syncthreads();
    }

    // normalize + store fp16 (feeds Wp GEMM)
    const float il0 = 1.0f / sL[wm0 + g];
    const float il1 = 1.0f / sL[wm0 + g + 8];
    __half* yg = y + (size_t)b * SEQ * D_MODEL + (size_t)h * HDIM;
#pragma unroll
    for (int nf = 0; nf < 8; nf++) {
        const int col = nf * 8 + t * 2;
        const int r0 = q0 + wm0 + g;
        __half2 o0;
        o0.x = __float2half_rn(o[nf][0] * il0);
        o0.y = __float2half_rn(o[nf][1] * il0);
        *(__half2*)(yg + (size_t)r0 * D_MODEL + col) = o0;
        __half2 o1;
        o1.x = __float2half_rn(o[nf][2] * il1);
        o1.y = __float2half_rn(o[nf][3] * il1);
        *(__half2*)(yg + (size_t)(r0 + 8) * D_MODEL + col) = o1;
    }
}

// ===========================================================================
// launch
// ===========================================================================
extern "C" void kernel_launch(void* const* d_in, const int* in_sizes, int n_in,
                              void* d_out, int out_size) {
    const float* x   = (const float*)d_in[0];
    const float* Wk  = (const float*)d_in[1];
    const float* Wq  = (const float*)d_in[2];
    const float* Wv  = (const float*)d_in[3];
    const float* Wp  = (const float*)d_in[4];
    const float* bp  = (const float*)d_in[5];
    const float* g1  = (const float*)d_in[6];
    const float* b1  = (const float*)d_in[7];
    const float* g2  = (const float*)d_in[8];
    const float* b2  = (const float*)d_in[9];
    const float* W1  = (const float*)d_in[10];
    const float* bm1 = (const float*)d_in[11];
    const float* W2  = (const float*)d_in[12];
    const float* bm2 = (const float*)d_in[13];
    float* out = (float*)d_out;

    float* S = nullptr;
    cudaGetSymbolAddress((void**)&S, g_scratch);
    float*  xn    = S + 0 * CH;                       // fp32 residual
    __half* xnh   = (__half*)(S + 1 * CH);            // 4M halves
    __half* qkv   = (__half*)(S + 2 * CH);            // 12M halves (chunks 2-3)
    __half* yb    = (__half*)(S + 4 * CH);            // 4M halves
    float*  hb    = S + 5 * CH;                       // fp32
    __half* hn    = (__half*)(S + 6 * CH);            // 4M halves
    __half* m1    = (__half*)(S + 7 * CH);            // 16M halves (chunks 7-8)
    __half* WqkvT = (__half*)(S + 9 * CH);            // 3M halves
    __half* WpT   = (__half*)(S + 10 * CH);           // 1M halves
    __half* W1T   = (__half*)(S + 11 * CH);           // 4M halves
    __half* W2T   = (__half*)(S + 12 * CH);           // 4M halves

    cudaFuncSetAttribute(attn_kernel, cudaFuncAttributeMaxDynamicSharedMemorySize,
                         ATT_SMEM);
    cudaFuncSetAttribute(tgemm<false>, cudaFuncAttributeMaxDynamicSharedMemorySize,
                         GEMM_SMEM);
    cudaFuncSetAttribute(tgemm<true>, cudaFuncAttributeMaxDynamicSharedMemorySize,
                         GEMM_SMEM);

    dim3 tb(32, 8);
    dim3 tg(D_MODEL / 32, D_MODEL / 32);

    // launches ordered so ncu -s 5 samples attn_kernel
    transpose_kernel<<<tg, tb>>>(Wq, WqkvT + 0 * D_MODEL * D_MODEL, D_MODEL, D_MODEL); // 0
    transpose_kernel<<<tg, tb>>>(Wk, WqkvT + 1 * D_MODEL * D_MODEL, D_MODEL, D_MODEL); // 1
    transpose_kernel<<<tg, tb>>>(Wv, WqkvT + 2 * D_MODEL * D_MODEL, D_MODEL, D_MODEL); // 2

    ln_kernel<<<MROWS, 256>>>(x, g1, b1, xn, xnh);                                     // 3

    dim3 gqkv(QKVN / 128, MROWS / 128);
    tgemm<false><<<gqkv, 256, GEMM_SMEM>>>(xnh, WqkvT, nullptr, qkv,
                                           MROWS, QKVN, D_MODEL, nullptr, nullptr);   // 4

    dim3 ag(BATCH * NHEAD, SEQ / 64);
    attn_kernel<<<ag, 128, ATT_SMEM>>>(qkv, yb);                                       // 5

    transpose_kernel<<<tg, tb>>>(Wp, WpT, D_MODEL, D_MODEL);                           // 6

    dim3 g1024(D_MODEL / 128, MROWS / 128);
    tgemm<false><<<g1024, 256, GEMM_SMEM>>>(yb, WpT, hb, nullptr,
                                            MROWS, D_MODEL, D_MODEL, bp, xn);          // 7

    ln_kernel<<<MROWS, 256>>>(hb, g2, b2, nullptr, hn);                                // 8

    transpose_kernel<<<dim3(DFF/32, D_MODEL/32), tb>>>(W1, W1T, D_MODEL, DFF);         // 9
    dim3 g4096(DFF / 128, MROWS / 128);
    tgemm<true><<<g4096, 256, GEMM_SMEM>>>(hn, W1T, nullptr, m1,
                                           MROWS, DFF, D_MODEL, bm1, nullptr);         // 10

    transpose_kernel<<<dim3(D_MODEL/32, DFF/32), tb>>>(W2, W2T, DFF, D_MODEL);         // 11
    tgemm<false><<<g1024, 256, GEMM_SMEM>>>(m1, W2T, out, nullptr,
                                            MROWS, D_MODEL, DFF, bm2, hb);             // 12

    (void)in_sizes; (void)n_in; (void)out_size;
}

// round 7
// speedup vs baseline: 1.5030x; 1.1313x over previous
#include <cuda_runtime.h>
#include <cuda_fp16.h>
#include <math.h>
#include <stdint.h>

// ---------------------------------------------------------------------------
// TransformerSelfAttention: B=2, S=2048, D=1024, H=16, HD=64
// GEMMs + attention on mma.sync FP16 (m16n8k16, fp32 accum), ldmatrix feeds.
// ---------------------------------------------------------------------------

#define D_MODEL 1024
#define SEQ     2048
#define BATCH   2
#define NHEAD   16
#define HDIM    64
#define MROWS   (BATCH * SEQ)        // 4096
#define DFF     (4 * D_MODEL)        // 4096
#define QKVN    (3 * D_MODEL)        // 3072

#define CH      (4u * 1024u * 1024u) // 4M floats chunk
__device__ float g_scratch[56u * 1024u * 1024u];

// ===========================================================================
// helpers
// ===========================================================================
__device__ __forceinline__ uint32_t smem_u32(const void* p) {
    uint32_t a;
    asm("{ .reg .u64 t; cvta.to.shared.u64 t, %1; cvt.u32.u64 %0, t; }"
        : "=r"(a) : "l"(p));
    return a;
}

#define CP_ASYNC16(dst, src) \
    asm volatile("cp.async.cg.shared.global [%0], [%1], 16;" \
                 :: "r"(dst), "l"(src))
#define CP_COMMIT()  asm volatile("cp.async.commit_group;")
#define CP_WAIT0()   asm volatile("cp.async.wait_group 0;")

// m16n8k16 fp16 MMA, fp32 accumulate
__device__ __forceinline__ void mma_f16(float* c, const uint32_t* a,
                                        const uint32_t* b) {
    asm volatile(
        "mma.sync.aligned.m16n8k16.row.col.f32.f16.f16.f32 "
        "{%0,%1,%2,%3}, {%4,%5,%6,%7}, {%8,%9}, {%0,%1,%2,%3};"
        : "+f"(c[0]), "+f"(c[1]), "+f"(c[2]), "+f"(c[3])
        : "r"(a[0]), "r"(a[1]), "r"(a[2]), "r"(a[3]), "r"(b[0]), "r"(b[1]));
}

__device__ __forceinline__ void ldsm_x4(uint32_t* r, uint32_t addr) {
    asm volatile("ldmatrix.sync.aligned.m8n8.x4.shared.b16 {%0,%1,%2,%3}, [%4];"
        : "=r"(r[0]), "=r"(r[1]), "=r"(r[2]), "=r"(r[3]) : "r"(addr));
}

// ===========================================================================
// LayerNorm: fp32 out (residual) + fp16 out (GEMM operand)
// ===========================================================================
__global__ void ln_kernel(const float* __restrict__ x,
                          const float* __restrict__ g,
                          const float* __restrict__ b,
                          float* __restrict__ out,
                          __half* __restrict__ outh) {
    __shared__ float red[256], red2[256];
    __shared__ float s_mu, s_rstd;
    const int row = blockIdx.x;
    const int tid = threadIdx.x;
    const float* xr = x + (size_t)row * D_MODEL;

    float vals[4];
    float s = 0.f, s2 = 0.f;
#pragma unroll
    for (int i = 0; i < 4; i++) {
        float v = xr[tid + i * 256];
        vals[i] = v;
        s += v; s2 += v * v;
    }
    red[tid] = s; red2[tid] = s2;
    __syncthreads();
    for (int off = 128; off > 0; off >>= 1) {
        if (tid < off) { red[tid] += red[tid + off]; red2[tid] += red2[tid + off]; }
        __syncthreads();
    }
    if (tid == 0) {
        float mu = red[0] * (1.0f / D_MODEL);
        float var = red2[0] * (1.0f / D_MODEL) - mu * mu;
        s_mu = mu;
        s_rstd = rsqrtf(var + 1e-5f);
    }
    __syncthreads();
    const float mu = s_mu, rstd = s_rstd;
#pragma unroll
    for (int i = 0; i < 4; i++) {
        int c = tid + i * 256;
        float v = (vals[i] - mu) * rstd * g[c] + b[c];
        if (out)  out[(size_t)row * D_MODEL + c] = v;
        if (outh) outh[(size_t)row * D_MODEL + c] = __float2half_rn(v);
    }
}

// ===========================================================================
// Transpose: half out[C,R] = rne(in[R,C]^T)
// ===========================================================================
__global__ void transpose_kernel(const float* __restrict__ in,
                                 __half* __restrict__ out, int R, int C) {
    __shared__ float t[32][33];
    const int bx = blockIdx.x * 32, by = blockIdx.y * 32;
    const int tx = threadIdx.x, ty = threadIdx.y;
#pragma unroll
    for (int j = 0; j < 32; j += 8)
        t[ty + j][tx] = in[(size_t)(by + ty + j) * C + bx + tx];
    __syncthreads();
#pragma unroll
    for (int j = 0; j < 32; j += 8)
        out[(size_t)(bx + ty + j) * R + by + tx] = __float2half_rn(t[tx][ty + j]);
}

// ===========================================================================
// FP16 mma GEMM: C = A[M,K] @ Bt[N,K]^T (+bias)(gelu)(+residual)
// 128x128 CTA tile, BK=64, 8 warps (2Mx4N), ldmatrix fragment loads.
// ===========================================================================
#define LDH 72                         // halves per SMEM row (64 data + 8 pad)
#define TILE_H (128 * LDH)             // halves per tile
#define STAGE_B (2 * TILE_H * 2)       // bytes per stage (A+B) = 36864
#define GEMM_SMEM (2 * STAGE_B)        // 73728 bytes

__device__ __forceinline__ void tile_load_h(const __half* __restrict__ Ag,
                                            const __half* __restrict__ Bg,
                                            int K, int it, uint32_t sbu, int tid) {
    const uint32_t dst = sbu + (uint32_t)(it & 1) * STAGE_B;
#pragma unroll
    for (int j = 0; j < 4; j++) {
        const int idx = tid + j * 256;           // 0..1023
        const int row = idx >> 3;
        const int c = idx & 7;                   // 16B chunk (8 halves)
        const uint32_t so = (uint32_t)(row * LDH + c * 8) * 2;
        const __half* ga = Ag + (size_t)row * K + it * 64 + c * 8;
        const __half* gb = Bg + (size_t)row * K + it * 64 + c * 8;
        CP_ASYNC16(dst + so, ga);
        CP_ASYNC16(dst + TILE_H * 2 + so, gb);
    }
    CP_COMMIT();
}

template <bool GELU>
__global__ __launch_bounds__(256, 2)
void tgemm(const __half* __restrict__ A, const __half* __restrict__ Bt,
           float* __restrict__ Cf, __half* __restrict__ Chh,
           int M, int N, int K,
           const float* __restrict__ bias, const float* __restrict__ residual) {
    extern __shared__ char smraw[];
    const uint32_t sbu = smem_u32(smraw);

    const int tid = threadIdx.x;
    const int w = tid >> 5, lane = tid & 31;
    const int g = lane >> 2, t = lane & 3;
    const int wm = w & 1, wn = w >> 1;
    const int m0 = blockIdx.y * 128, n0 = blockIdx.x * 128;
    const __half* Ag = A + (size_t)m0 * K;
    const __half* Bg = Bt + (size_t)n0 * K;
    const int nk = K >> 6;

    // ldmatrix lane address components (halves)
    const int a_r = lane & 15;               // row within m16 fragment
    const int a_c = (lane >> 4) << 3;        // k-offset 0/8
    const int b_r = ((lane >> 4) << 3) + (lane & 7);  // row within n16 pair
    const int b_c = ((lane >> 3) & 1) << 3;  // k-offset 0/8

    float c[4][4][4];
#pragma unroll
    for (int i = 0; i < 4; i++)
#pragma unroll
        for (int j = 0; j < 4; j++)
#pragma unroll
            for (int q = 0; q < 4; q++) c[i][j][q] = 0.f;

    tile_load_h(Ag, Bg, K, 0, sbu, tid);

    for (int it = 0; it < nk; it++) {
        CP_WAIT0();
        __syncthreads();
        if (it + 1 < nk) tile_load_h(Ag, Bg, K, it + 1, sbu, tid);

        const uint32_t sa = sbu + (uint32_t)(it & 1) * STAGE_B;
        const uint32_t sb = sa + TILE_H * 2;
#pragma unroll
        for (int ks = 0; ks < 4; ks++) {           // 4 x k16
            const int kk = ks * 16;
            uint32_t ar[4][4];
#pragma unroll
            for (int mf = 0; mf < 4; mf++)
                ldsm_x4(ar[mf], sa + (uint32_t)((wm * 64 + mf * 16 + a_r) * LDH
                                                + kk + a_c) * 2);
            uint32_t br[4][2];
#pragma unroll
            for (int p = 0; p < 2; p++) {
                uint32_t r4[4];
                ldsm_x4(r4, sb + (uint32_t)((wn * 32 + p * 16 + b_r) * LDH
                                            + kk + b_c) * 2);
                br[2 * p][0] = r4[0]; br[2 * p][1] = r4[1];
                br[2 * p + 1][0] = r4[2]; br[2 * p + 1][1] = r4[3];
            }
#pragma unroll
            for (int mf = 0; mf < 4; mf++)
#pragma unroll
                for (int nf = 0; nf < 4; nf++)
                    mma_f16(c[mf][nf], ar[mf], br[nf]);
        }
        __syncthreads();
    }

#pragma unroll
    for (int mf = 0; mf < 4; mf++) {
        const int r0 = m0 + wm * 64 + mf * 16 + g;
#pragma unroll
        for (int half = 0; half < 2; half++) {
            const int row = r0 + half * 8;
            const float* rrow = residual ? residual + (size_t)row * N : nullptr;
#pragma unroll
            for (int nf = 0; nf < 4; nf++) {
                const int col = n0 + wn * 32 + nf * 8 + t * 2;
                float v0 = c[mf][nf][half * 2 + 0];
                float v1 = c[mf][nf][half * 2 + 1];
                if (bias) { v0 += bias[col]; v1 += bias[col + 1]; }
                if (GELU) {
                    v0 = 0.5f * v0 * (1.0f + erff(v0 * 0.70710678118654752f));
                    v1 = 0.5f * v1 * (1.0f + erff(v1 * 0.70710678118654752f));
                }
                if (rrow) { v0 += rrow[col]; v1 += rrow[col + 1]; }
                if (Cf) {
                    float2 o; o.x = v0; o.y = v1;
                    *(float2*)(Cf + (size_t)row * N + col) = o;
                }
                if (Chh) {
                    __half2 oh;
                    oh.x = __float2half_rn(v0); oh.y = __float2half_rn(v1);
                    *(__half2*)(Chh + (size_t)row * N + col) = oh;
                }
            }
        }
    }
    (void)M;
}

// ===========================================================================
// Flash attention, fp16 mma + ldmatrix. qkv packed [MROWS, 3072] half.
// Per CTA: one (b,h), 64 q-rows, 4 warps. Output y fp16.
// ===========================================================================
#define LQH 72     // halves per SMEM row (64 data + 8 pad)
#define SLD 68     // fp32 score row stride
#define SQ_OFF   0
#define SK_OFF   (SQ_OFF + 64 * LQH * 2)
#define SVT_OFF  (SK_OFF + 64 * LQH * 2)
#define SP_OFF   (SVT_OFF + 64 * LQH * 2)
#define SS_OFF   (SP_OFF + 64 * LQH * 2)
#define STAT_OFF (SS_OFF + 64 * SLD * 4)
#define ATT_SMEM (STAT_OFF + 3 * 64 * 4)
#define QS QKVN

__global__ __launch_bounds__(128)
void attn_kernel(const __half* __restrict__ qkv, __half* __restrict__ y) {
    extern __shared__ char smraw[];
    __half* sQ  = (__half*)(smraw + SQ_OFF);
    __half* sK  = (__half*)(smraw + SK_OFF);
    __half* sVt = (__half*)(smraw + SVT_OFF);
    __half* sP  = (__half*)(smraw + SP_OFF);
    float*  sS  = (float*)(smraw + SS_OFF);
    float*  sM  = (float*)(smraw + STAT_OFF);
    float*  sL  = sM + 64;
    float*  sA  = sL + 64;
    const uint32_t su = smem_u32(smraw);

    const int tid  = threadIdx.x;
    const int wid  = tid >> 5;
    const int lane = tid & 31;
    const int g = lane >> 2, t = lane & 3;
    const int wm0 = wid * 16;

    const int a_r = lane & 15;
    const int a_c = (lane >> 4) << 3;
    const int b_r = ((lane >> 4) << 3) + (lane & 7);
    const int b_c = ((lane >> 3) & 1) << 3;

    const int bh = blockIdx.x;
    const int b  = bh >> 4;
    const int h  = bh & 15;
    const int q0 = blockIdx.y * 64;

    const size_t baseq = (size_t)b * SEQ * QS + (size_t)h * HDIM;
    const __half* qg = qkv + baseq;
    const __half* kg = qkv + baseq + D_MODEL;
    const __half* vg = qkv + baseq + 2 * D_MODEL;

#pragma unroll
    for (int j = 0; j < 4; j++) {
        const int idx = tid + j * 128;
        const int r = idx >> 3, c = idx & 7;
        uint4 tq = *(const uint4*)(qg + (size_t)(q0 + r) * QS + c * 8);
        *(uint4*)(sQ + r * LQH + c * 8) = tq;
    }
    if (tid < 64) { sM[tid] = -INFINITY; sL[tid] = 0.f; }

    float o[8][4];
#pragma unroll
    for (int i = 0; i < 8; i++)
#pragma unroll
        for (int j = 0; j < 4; j++) o[i][j] = 0.f;

    __syncthreads();

    for (int kt = 0; kt < SEQ / 64; kt++) {
        const int k0 = kt * 64;
#pragma unroll
        for (int j = 0; j < 4; j++) {
            const int idx = tid + j * 128;
            const int r = idx >> 3, c = idx & 7;
            uint4 tk = *(const uint4*)(kg + (size_t)(k0 + r) * QS + c * 8);
            *(uint4*)(sK + r * LQH + c * 8) = tk;
            uint4 tv = *(const uint4*)(vg + (size_t)(k0 + r) * QS + c * 8);
            const __half* hv = (const __half*)&tv;
#pragma unroll
            for (int q = 0; q < 8; q++)
                sVt[(c * 8 + q) * LQH + r] = hv[q];
        }
        __syncthreads();

        // S = Q @ K^T
        float sacc[8][4];
#pragma unroll
        for (int i = 0; i < 8; i++)
#pragma unroll
            for (int j = 0; j < 4; j++) sacc[i][j] = 0.f;
#pragma unroll
        for (int ks = 0; ks < 4; ks++) {
            const int kk = ks * 16;
            uint32_t a[4];
            ldsm_x4(a, su + SQ_OFF + (uint32_t)((wm0 + a_r) * LQH + kk + a_c) * 2);
#pragma unroll
            for (int p = 0; p < 4; p++) {
                uint32_t r4[4];
                ldsm_x4(r4, su + SK_OFF + (uint32_t)((p * 16 + b_r) * LQH
                                                     + kk + b_c) * 2);
                mma_f16(sacc[2 * p + 0], a, r4);
                mma_f16(sacc[2 * p + 1], a, r4 + 2);
            }
        }

        // scale + diag mask -> sS (fp32)
        const float scale = 0.125f;
#pragma unroll
        for (int nf = 0; nf < 8; nf++) {
            const int col = nf * 8 + t * 2;
#pragma unroll
            for (int half = 0; half < 2; half++) {
                const int r = wm0 + g + half * 8;
                float v0 = sacc[nf][half * 2 + 0] * scale;
                float v1 = sacc[nf][half * 2 + 1] * scale;
                if (q0 + r == k0 + col)     v0 = -INFINITY;
                if (q0 + r == k0 + col + 1) v1 = -INFINITY;
                float2 pv; pv.x = v0; pv.y = v1;
                *(float2*)(sS + r * SLD + col) = pv;
            }
        }
        __syncthreads();

        // online softmax: 2 threads/row, write P as fp16
        {
            const int r = tid >> 1, hf = tid & 1;
            const float* row = sS + r * SLD + hf * 32;
            __half* prow = sP + r * LQH + hf * 32;
            float mt = -INFINITY;
#pragma unroll 8
            for (int c = 0; c < 32; c++) mt = fmaxf(mt, row[c]);
            mt = fmaxf(mt, __shfl_xor_sync(0xffffffffu, mt, 1));
            const float mold = sM[r];
            const float mnew = fmaxf(mold, mt);
            float ps = 0.f;
#pragma unroll 8
            for (int c = 0; c < 32; c++) {
                float p = __expf(row[c] - mnew);
                prow[c] = __float2half_rn(p);
                ps += p;
            }
            ps += __shfl_xor_sync(0xffffffffu, ps, 1);
            if (hf == 0) {
                const float alpha = __expf(mold - mnew);
                sL[r] = sL[r] * alpha + ps;
                sM[r] = mnew;
                sA[r] = alpha;
            }
        }
        __syncthreads();

        // O = O*alpha + P @ V
        const float al0 = sA[wm0 + g];
        const float al1 = sA[wm0 + g + 8];
#pragma unroll
        for (int nf = 0; nf < 8; nf++) {
            o[nf][0] *= al0; o[nf][1] *= al0;
            o[nf][2] *= al1; o[nf][3] *= al1;
        }
#pragma unroll
        for (int ks = 0; ks < 4; ks++) {
            const int kk = ks * 16;
            uint32_t a[4];
            ldsm_x4(a, su + SP_OFF + (uint32_t)((wm0 + a_r) * LQH + kk + a_c) * 2);
#pragma unroll
            for (int p = 0; p < 4; p++) {
                uint32_t r4[4];
                ldsm_x4(r4, su + SVT_OFF + (uint32_t)((p * 16 + b_r) * LQH
                                                      + kk + b_c) * 2);
                mma_f16(o[2 * p + 0], a, r4);
                mma_f16(o[2 * p + 1], a, r4 + 2);
            }
        }
        __syncthreads();
    }

    // normalize + store fp16 (feeds Wp GEMM)
    const float il0 = 1.0f / sL[wm0 + g];
    const float il1 = 1.0f / sL[wm0 + g + 8];
    __half* yg = y + (size_t)b * SEQ * D_MODEL + (size_t)h * HDIM;
#pragma unroll
    for (int nf = 0; nf < 8; nf++) {
        const int col = nf * 8 + t * 2;
        const int r0 = q0 + wm0 + g;
        __half2 o0;
        o0.x = __float2half_rn(o[nf][0] * il0);
        o0.y = __float2half_rn(o[nf][1] * il0);
        *(__half2*)(yg + (size_t)r0 * D_MODEL + col) = o0;
        __half2 o1;
        o1.x = __float2half_rn(o[nf][2] * il1);
        o1.y = __float2half_rn(o[nf][3] * il1);
        *(__half2*)(yg + (size_t)(r0 + 8) * D_MODEL + col) = o1;
    }
}

// ===========================================================================
// launch
// ===========================================================================
extern "C" void kernel_launch(void* const* d_in, const int* in_sizes, int n_in,
                              void* d_out, int out_size) {
    const float* x   = (const float*)d_in[0];
    const float* Wk  = (const float*)d_in[1];
    const float* Wq  = (const float*)d_in[2];
    const float* Wv  = (const float*)d_in[3];
    const float* Wp  = (const float*)d_in[4];
    const float* bp  = (const float*)d_in[5];
    const float* g1  = (const float*)d_in[6];
    const float* b1  = (const float*)d_in[7];
    const float* g2  = (const float*)d_in[8];
    const float* b2  = (const float*)d_in[9];
    const float* W1  = (const float*)d_in[10];
    const float* bm1 = (const float*)d_in[11];
    const float* W2  = (const float*)d_in[12];
    const float* bm2 = (const float*)d_in[13];
    float* out = (float*)d_out;

    float* S = nullptr;
    cudaGetSymbolAddress((void**)&S, g_scratch);
    float*  xn    = S + 0 * CH;
    __half* xnh   = (__half*)(S + 1 * CH);
    __half* qkv   = (__half*)(S + 2 * CH);            // 12M halves (chunks 2-3)
    __half* yb    = (__half*)(S + 4 * CH);
    float*  hb    = S + 5 * CH;
    __half* hn    = (__half*)(S + 6 * CH);
    __half* m1    = (__half*)(S + 7 * CH);            // 16M halves (chunks 7-8)
    __half* WqkvT = (__half*)(S + 9 * CH);
    __half* WpT   = (__half*)(S + 10 * CH);
    __half* W1T   = (__half*)(S + 11 * CH);
    __half* W2T   = (__half*)(S + 12 * CH);

    cudaFuncSetAttribute(attn_kernel, cudaFuncAttributeMaxDynamicSharedMemorySize,
                         ATT_SMEM);
    cudaFuncSetAttribute(tgemm<false>, cudaFuncAttributeMaxDynamicSharedMemorySize,
                         GEMM_SMEM);
    cudaFuncSetAttribute(tgemm<true>, cudaFuncAttributeMaxDynamicSharedMemorySize,
                         GEMM_SMEM);

    dim3 tb(32, 8);
    dim3 tg(D_MODEL / 32, D_MODEL / 32);

    transpose_kernel<<<tg, tb>>>(Wq, WqkvT + 0 * D_MODEL * D_MODEL, D_MODEL, D_MODEL);
    transpose_kernel<<<tg, tb>>>(Wk, WqkvT + 1 * D_MODEL * D_MODEL, D_MODEL, D_MODEL);
    transpose_kernel<<<tg, tb>>>(Wv, WqkvT + 2 * D_MODEL * D_MODEL, D_MODEL, D_MODEL);

    ln_kernel<<<MROWS, 256>>>(x, g1, b1, xn, xnh);

    dim3 gqkv(QKVN / 128, MROWS / 128);
    tgemm<false><<<gqkv, 256, GEMM_SMEM>>>(xnh, WqkvT, nullptr, qkv,
                                           MROWS, QKVN, D_MODEL, nullptr, nullptr);

    dim3 ag(BATCH * NHEAD, SEQ / 64);
    attn_kernel<<<ag, 128, ATT_SMEM>>>(qkv, yb);

    transpose_kernel<<<tg, tb>>>(Wp, WpT, D_MODEL, D_MODEL);

    dim3 g1024(D_MODEL / 128, MROWS / 128);
    tgemm<false><<<g1024, 256, GEMM_SMEM>>>(yb, WpT, hb, nullptr,
                                            MROWS, D_MODEL, D_MODEL, bp, xn);

    ln_kernel<<<MROWS, 256>>>(hb, g2, b2, nullptr, hn);

    transpose_kernel<<<dim3(DFF/32, D_MODEL/32), tb>>>(W1, W1T, D_MODEL, DFF);
    dim3 g4096(DFF / 128, MROWS / 128);
    tgemm<true><<<g4096, 256, GEMM_SMEM>>>(hn, W1T, nullptr, m1,
                                           MROWS, DFF, D_MODEL, bm1, nullptr);

    transpose_kernel<<<dim3(D_MODEL/32, DFF/32), tb>>>(W2, W2T, DFF, D_MODEL);
    tgemm<false><<<g1024, 256, GEMM_SMEM>>>(m1, W2T, out, nullptr,
                                            MROWS, D_MODEL, DFF, bm2, hb);

    (void)in_sizes; (void)n_in; (void)out_size;
}

// round 8
// speedup vs baseline: 2.2235x; 1.4794x over previous
#include <cuda_runtime.h>
#include <cuda_fp16.h>
#include <math.h>
#include <stdint.h>

// ---------------------------------------------------------------------------
// TransformerSelfAttention: B=2, S=2048, D=1024, H=16, HD=64
// fp16 mma.sync m16n8k16 everywhere; ldmatrix (+.trans for B operands);
// register-resident online softmax in attention.
// ---------------------------------------------------------------------------

#define D_MODEL 1024
#define SEQ     2048
#define BATCH   2
#define NHEAD   16
#define HDIM    64
#define MROWS   (BATCH * SEQ)        // 4096
#define DFF     (4 * D_MODEL)        // 4096
#define QKVN    (3 * D_MODEL)        // 3072

#define CH      (4u * 1024u * 1024u) // 4M floats chunk
__device__ float g_scratch[56u * 1024u * 1024u];

// ===========================================================================
// helpers
// ===========================================================================
__device__ __forceinline__ uint32_t smem_u32(const void* p) {
    uint32_t a;
    asm("{ .reg .u64 t; cvta.to.shared.u64 t, %1; cvt.u32.u64 %0, t; }"
        : "=r"(a) : "l"(p));
    return a;
}

#define CP_ASYNC16(dst, src) \
    asm volatile("cp.async.cg.shared.global [%0], [%1], 16;" \
                 :: "r"(dst), "l"(src))
#define CP_COMMIT()  asm volatile("cp.async.commit_group;")
#define CP_WAIT0()   asm volatile("cp.async.wait_group 0;")

__device__ __forceinline__ void mma_f16(float* c, const uint32_t* a,
                                        const uint32_t* b) {
    asm volatile(
        "mma.sync.aligned.m16n8k16.row.col.f32.f16.f16.f32 "
        "{%0,%1,%2,%3}, {%4,%5,%6,%7}, {%8,%9}, {%0,%1,%2,%3};"
        : "+f"(c[0]), "+f"(c[1]), "+f"(c[2]), "+f"(c[3])
        : "r"(a[0]), "r"(a[1]), "r"(a[2]), "r"(a[3]), "r"(b[0]), "r"(b[1]));
}

__device__ __forceinline__ void ldsm_x4(uint32_t* r, uint32_t addr) {
    asm volatile("ldmatrix.sync.aligned.m8n8.x4.shared.b16 {%0,%1,%2,%3}, [%4];"
        : "=r"(r[0]), "=r"(r[1]), "=r"(r[2]), "=r"(r[3]) : "r"(addr));
}
__device__ __forceinline__ void ldsm_x4_t(uint32_t* r, uint32_t addr) {
    asm volatile("ldmatrix.sync.aligned.m8n8.x4.trans.shared.b16 {%0,%1,%2,%3}, [%4];"
        : "=r"(r[0]), "=r"(r[1]), "=r"(r[2]), "=r"(r[3]) : "r"(addr));
}

// ===========================================================================
// LayerNorm: fp32 out (residual) + fp16 out (GEMM operand)
// ===========================================================================
__global__ void ln_kernel(const float* __restrict__ x,
                          const float* __restrict__ g,
                          const float* __restrict__ b,
                          float* __restrict__ out,
                          __half* __restrict__ outh) {
    __shared__ float red[256], red2[256];
    __shared__ float s_mu, s_rstd;
    const int row = blockIdx.x;
    const int tid = threadIdx.x;
    const float* xr = x + (size_t)row * D_MODEL;

    float vals[4];
    float s = 0.f, s2 = 0.f;
#pragma unroll
    for (int i = 0; i < 4; i++) {
        float v = xr[tid + i * 256];
        vals[i] = v;
        s += v; s2 += v * v;
    }
    red[tid] = s; red2[tid] = s2;
    __syncthreads();
    for (int off = 128; off > 0; off >>= 1) {
        if (tid < off) { red[tid] += red[tid + off]; red2[tid] += red2[tid + off]; }
        __syncthreads();
    }
    if (tid == 0) {
        float mu = red[0] * (1.0f / D_MODEL);
        float var = red2[0] * (1.0f / D_MODEL) - mu * mu;
        s_mu = mu;
        s_rstd = rsqrtf(var + 1e-5f);
    }
    __syncthreads();
    const float mu = s_mu, rstd = s_rstd;
#pragma unroll
    for (int i = 0; i < 4; i++) {
        int c = tid + i * 256;
        float v = (vals[i] - mu) * rstd * g[c] + b[c];
        if (out)  out[(size_t)row * D_MODEL + c] = v;
        if (outh) outh[(size_t)row * D_MODEL + c] = __float2half_rn(v);
    }
}

// ===========================================================================
// Weight converts (fp32 -> fp16, layout preserved)
// ===========================================================================
__global__ void convert_kernel(const float* __restrict__ in,
                               __half* __restrict__ out, int n) {
    const int i = (blockIdx.x * 256 + threadIdx.x) * 4;
    if (i < n) {
        float4 v = *(const float4*)(in + i);
        __half2 a, b2;
        a.x = __float2half_rn(v.x); a.y = __float2half_rn(v.y);
        b2.x = __float2half_rn(v.z); b2.y = __float2half_rn(v.w);
        *(__half2*)(out + i) = a;
        *(__half2*)(out + i + 2) = b2;
    }
}

// pack Wq|Wk|Wv ([K,1024] each) into [K, 3072] fp16
__global__ void convert_pack_qkv(const float* __restrict__ Wq,
                                 const float* __restrict__ Wk,
                                 const float* __restrict__ Wv,
                                 __half* __restrict__ out) {
    const int idx = (blockIdx.x * 256 + threadIdx.x) * 4;   // over K*3072
    const int k = idx / QKVN;
    const int n = idx % QKVN;
    const float* src = (n < D_MODEL) ? Wq : (n < 2 * D_MODEL ? Wk : Wv);
    const int nn = n & (D_MODEL - 1);
    float4 v = *(const float4*)(src + (size_t)k * D_MODEL + nn);
    __half2 a, b2;
    a.x = __float2half_rn(v.x); a.y = __float2half_rn(v.y);
    b2.x = __float2half_rn(v.z); b2.y = __float2half_rn(v.w);
    *(__half2*)(out + idx) = a;
    *(__half2*)(out + idx + 2) = b2;
}

// ===========================================================================
// FP16 mma GEMM: C = A[M,K] @ B[K,N] (+bias)(gelu)(+residual)
// 128x128 CTA tile, BK=64, 8 warps (2Mx4N). A: ldmatrix; B: ldmatrix.trans.
// ===========================================================================
#define LDH 72                          // A smem row (64 data + 8 pad) halves
#define LDB 136                         // B smem row (128 data + 8 pad) halves
#define A_TILE_B (128 * LDH * 2)        // 18432
#define B_TILE_B (64 * LDB * 2)         // 17408
#define STAGE_B  (A_TILE_B + B_TILE_B)  // 35840
#define GEMM_SMEM (2 * STAGE_B)         // 71680

__device__ __forceinline__ void tile_load_h(const __half* __restrict__ Ag,
                                            const __half* __restrict__ Bg,
                                            int K, int N, int it,
                                            uint32_t sbu, int tid) {
    const uint32_t dst = sbu + (uint32_t)(it & 1) * STAGE_B;
    // A: 128 rows x 64 halves = 1024 x 16B chunks
#pragma unroll
    for (int j = 0; j < 4; j++) {
        const int idx = tid + j * 256;
        const int row = idx >> 3;
        const int c = idx & 7;
        CP_ASYNC16(dst + (uint32_t)(row * LDH + c * 8) * 2,
                   Ag + (size_t)row * K + it * 64 + c * 8);
    }
    // B: 64 rows x 128 halves = 1024 x 16B chunks (row-major [K,N] slice)
    const __half* Bg2 = Bg + (size_t)(it * 64) * N;
#pragma unroll
    for (int j = 0; j < 4; j++) {
        const int idx = tid + j * 256;
        const int row = idx >> 4;
        const int c = idx & 15;
        CP_ASYNC16(dst + A_TILE_B + (uint32_t)(row * LDB + c * 8) * 2,
                   Bg2 + (size_t)row * N + c * 8);
    }
    CP_COMMIT();
}

template <bool GELU>
__global__ __launch_bounds__(256, 2)
void tgemm(const __half* __restrict__ A, const __half* __restrict__ B,
           float* __restrict__ Cf, __half* __restrict__ Chh,
           int M, int N, int K,
           const float* __restrict__ bias, const float* __restrict__ residual) {
    extern __shared__ char smraw[];
    const uint32_t sbu = smem_u32(smraw);

    const int tid = threadIdx.x;
    const int w = tid >> 5, lane = tid & 31;
    const int g = lane >> 2, t = lane & 3;
    const int wm = w & 1, wn = w >> 1;
    const int m0 = blockIdx.y * 128, n0 = blockIdx.x * 128;
    const __half* Ag = A + (size_t)m0 * K;
    const __half* Bg = B + n0;
    const int nk = K >> 6;

    const int a_r = lane & 15;
    const int a_c = (lane >> 4) << 3;
    const int tr_r = (((lane >> 3) & 1) << 3) + (lane & 7);  // k row
    const int tr_c = (lane >> 4) << 3;                        // n col offset

    float c[4][4][4];
#pragma unroll
    for (int i = 0; i < 4; i++)
#pragma unroll
        for (int j = 0; j < 4; j++)
#pragma unroll
            for (int q = 0; q < 4; q++) c[i][j][q] = 0.f;

    tile_load_h(Ag, Bg, K, N, 0, sbu, tid);

    for (int it = 0; it < nk; it++) {
        CP_WAIT0();
        __syncthreads();
        if (it + 1 < nk) tile_load_h(Ag, Bg, K, N, it + 1, sbu, tid);

        const uint32_t sa = sbu + (uint32_t)(it & 1) * STAGE_B;
        const uint32_t sb = sa + A_TILE_B;
#pragma unroll
        for (int ks = 0; ks < 4; ks++) {           // 4 x k16
            const int kk = ks * 16;
            uint32_t ar[4][4];
#pragma unroll
            for (int mf = 0; mf < 4; mf++)
                ldsm_x4(ar[mf], sa + (uint32_t)((wm * 64 + mf * 16 + a_r) * LDH
                                                + kk + a_c) * 2);
            uint32_t br[4][2];
#pragma unroll
            for (int p = 0; p < 2; p++) {
                uint32_t r4[4];
                ldsm_x4_t(r4, sb + (uint32_t)((kk + tr_r) * LDB
                                              + wn * 32 + p * 16 + tr_c) * 2);
                br[2 * p][0] = r4[0]; br[2 * p][1] = r4[1];
                br[2 * p + 1][0] = r4[2]; br[2 * p + 1][1] = r4[3];
            }
#pragma unroll
            for (int mf = 0; mf < 4; mf++)
#pragma unroll
                for (int nf = 0; nf < 4; nf++)
                    mma_f16(c[mf][nf], ar[mf], br[nf]);
        }
        __syncthreads();
    }

#pragma unroll
    for (int mf = 0; mf < 4; mf++) {
        const int r0 = m0 + wm * 64 + mf * 16 + g;
#pragma unroll
        for (int half = 0; half < 2; half++) {
            const int row = r0 + half * 8;
            const float* rrow = residual ? residual + (size_t)row * N : nullptr;
#pragma unroll
            for (int nf = 0; nf < 4; nf++) {
                const int col = n0 + wn * 32 + nf * 8 + t * 2;
                float v0 = c[mf][nf][half * 2 + 0];
                float v1 = c[mf][nf][half * 2 + 1];
                if (bias) { v0 += bias[col]; v1 += bias[col + 1]; }
                if (GELU) {
                    v0 = 0.5f * v0 * (1.0f + erff(v0 * 0.70710678118654752f));
                    v1 = 0.5f * v1 * (1.0f + erff(v1 * 0.70710678118654752f));
                }
                if (rrow) { v0 += rrow[col]; v1 += rrow[col + 1]; }
                if (Cf) {
                    float2 o; o.x = v0; o.y = v1;
                    *(float2*)(Cf + (size_t)row * N + col) = o;
                }
                if (Chh) {
                    __half2 oh;
                    oh.x = __float2half_rn(v0); oh.y = __float2half_rn(v1);
                    *(__half2*)(Chh + (size_t)row * N + col) = oh;
                }
            }
        }
    }
    (void)M;
}

// ===========================================================================
// Flash attention: fp16 mma, register softmax, V via ldmatrix.trans.
// Per CTA: one (b,h), 64 q-rows, 4 warps. qkv packed [MROWS, 3072] half.
// ===========================================================================
#define LQH 72
#define SQ_OFF   0
#define SK_OFF   (SQ_OFF + 64 * LQH * 2)
#define SV_OFF   (SK_OFF + 64 * LQH * 2)
#define SP_OFF   (SV_OFF + 64 * LQH * 2)
#define ATT_SMEM (SP_OFF + 64 * LQH * 2)
#define QS QKVN

__global__ __launch_bounds__(128)
void attn_kernel(const __half* __restrict__ qkv, __half* __restrict__ y) {
    extern __shared__ char smraw[];
    __half* sQ = (__half*)(smraw + SQ_OFF);
    __half* sK = (__half*)(smraw + SK_OFF);
    __half* sV = (__half*)(smraw + SV_OFF);
    __half* sP = (__half*)(smraw + SP_OFF);
    const uint32_t su = smem_u32(smraw);

    const int tid  = threadIdx.x;
    const int wid  = tid >> 5;
    const int lane = tid & 31;
    const int g = lane >> 2, t = lane & 3;
    const int wm0 = wid * 16;

    const int a_r = lane & 15;
    const int a_c = (lane >> 4) << 3;
    const int b_r = ((lane >> 4) << 3) + (lane & 7);
    const int b_c = ((lane >> 3) & 1) << 3;
    const int tr_r = (((lane >> 3) & 1) << 3) + (lane & 7);
    const int tr_c = (lane >> 4) << 3;

    const int bh = blockIdx.x;
    const int b  = bh >> 4;
    const int h  = bh & 15;
    const int q0 = blockIdx.y * 64;

    const size_t baseq = (size_t)b * SEQ * QS + (size_t)h * HDIM;
    const __half* qg = qkv + baseq;
    const __half* kg = qkv + baseq + D_MODEL;
    const __half* vg = qkv + baseq + 2 * D_MODEL;

#pragma unroll
    for (int j = 0; j < 4; j++) {
        const int idx = tid + j * 128;
        const int r = idx >> 3, c = idx & 7;
        uint4 tq = *(const uint4*)(qg + (size_t)(q0 + r) * QS + c * 8);
        *(uint4*)(sQ + r * LQH + c * 8) = tq;
    }

    // register-resident stats (rows wm0+g and wm0+g+8; replicated over quad)
    float m0_ = -INFINITY, l0_ = 0.f;
    float m1_ = -INFINITY, l1_ = 0.f;

    float o[8][4];
#pragma unroll
    for (int i = 0; i < 8; i++)
#pragma unroll
        for (int j = 0; j < 4; j++) o[i][j] = 0.f;

    __syncthreads();

    for (int kt = 0; kt < SEQ / 64; kt++) {
        const int k0 = kt * 64;
        // load K, V tiles (row-major, vectorized)
#pragma unroll
        for (int j = 0; j < 4; j++) {
            const int idx = tid + j * 128;
            const int r = idx >> 3, c = idx & 7;
            uint4 tk = *(const uint4*)(kg + (size_t)(k0 + r) * QS + c * 8);
            *(uint4*)(sK + r * LQH + c * 8) = tk;
            uint4 tv = *(const uint4*)(vg + (size_t)(k0 + r) * QS + c * 8);
            *(uint4*)(sV + r * LQH + c * 8) = tv;
        }
        __syncthreads();

        // S = Q @ K^T   (m16 x n64)
        float sacc[8][4];
#pragma unroll
        for (int i = 0; i < 8; i++)
#pragma unroll
            for (int j = 0; j < 4; j++) sacc[i][j] = 0.f;
#pragma unroll
        for (int ks = 0; ks < 4; ks++) {
            const int kk = ks * 16;
            uint32_t a[4];
            ldsm_x4(a, su + SQ_OFF + (uint32_t)((wm0 + a_r) * LQH + kk + a_c) * 2);
#pragma unroll
            for (int p = 0; p < 4; p++) {
                uint32_t r4[4];
                ldsm_x4(r4, su + SK_OFF + (uint32_t)((p * 16 + b_r) * LQH
                                                     + kk + b_c) * 2);
                mma_f16(sacc[2 * p + 0], a, r4);
                mma_f16(sacc[2 * p + 1], a, r4 + 2);
            }
        }

        // scale + diag mask (in registers)
        const float scale = 0.125f;
        const int r0g = q0 + wm0 + g;        // global row of half 0
#pragma unroll
        for (int nf = 0; nf < 8; nf++) {
            const int col = k0 + nf * 8 + t * 2;
#pragma unroll
            for (int q = 0; q < 4; q++) sacc[nf][q] *= scale;
            if (r0g == col)          sacc[nf][0] = -INFINITY;
            if (r0g == col + 1)      sacc[nf][1] = -INFINITY;
            if (r0g + 8 == col)      sacc[nf][2] = -INFINITY;
            if (r0g + 8 == col + 1)  sacc[nf][3] = -INFINITY;
        }

        // online softmax in registers (quad reduction over t)
        float mt0 = -INFINITY, mt1 = -INFINITY;
#pragma unroll
        for (int nf = 0; nf < 8; nf++) {
            mt0 = fmaxf(mt0, fmaxf(sacc[nf][0], sacc[nf][1]));
            mt1 = fmaxf(mt1, fmaxf(sacc[nf][2], sacc[nf][3]));
        }
        mt0 = fmaxf(mt0, __shfl_xor_sync(0xffffffffu, mt0, 1));
        mt0 = fmaxf(mt0, __shfl_xor_sync(0xffffffffu, mt0, 2));
        mt1 = fmaxf(mt1, __shfl_xor_sync(0xffffffffu, mt1, 1));
        mt1 = fmaxf(mt1, __shfl_xor_sync(0xffffffffu, mt1, 2));
        const float mn0 = fmaxf(m0_, mt0);
        const float mn1 = fmaxf(m1_, mt1);
        const float al0 = __expf(m0_ - mn0);
        const float al1 = __expf(m1_ - mn1);
        float ps0 = 0.f, ps1 = 0.f;
        __half* p0row = sP + (wm0 + g) * LQH + t * 2;
        __half* p1row = sP + (wm0 + g + 8) * LQH + t * 2;
#pragma unroll
        for (int nf = 0; nf < 8; nf++) {
            float e0 = __expf(sacc[nf][0] - mn0);
            float e1 = __expf(sacc[nf][1] - mn0);
            float e2 = __expf(sacc[nf][2] - mn1);
            float e3 = __expf(sacc[nf][3] - mn1);
            ps0 += e0 + e1; ps1 += e2 + e3;
            __half2 h0; h0.x = __float2half_rn(e0); h0.y = __float2half_rn(e1);
            __half2 h1; h1.x = __float2half_rn(e2); h1.y = __float2half_rn(e3);
            *(__half2*)(p0row + nf * 8) = h0;
            *(__half2*)(p1row + nf * 8) = h1;
        }
        ps0 += __shfl_xor_sync(0xffffffffu, ps0, 1);
        ps0 += __shfl_xor_sync(0xffffffffu, ps0, 2);
        ps1 += __shfl_xor_sync(0xffffffffu, ps1, 1);
        ps1 += __shfl_xor_sync(0xffffffffu, ps1, 2);
        l0_ = l0_ * al0 + ps0;  m0_ = mn0;
        l1_ = l1_ * al1 + ps1;  m1_ = mn1;

        // O *= alpha
#pragma unroll
        for (int nf = 0; nf < 8; nf++) {
            o[nf][0] *= al0; o[nf][1] *= al0;
            o[nf][2] *= al1; o[nf][3] *= al1;
        }
        __syncwarp();   // P writes -> ldmatrix (warp-internal)

        // O += P @ V  (V row-major, B operand via ldmatrix.trans)
#pragma unroll
        for (int ks = 0; ks < 4; ks++) {
            const int kk = ks * 16;
            uint32_t a[4];
            ldsm_x4(a, su + SP_OFF + (uint32_t)((wm0 + a_r) * LQH + kk + a_c) * 2);
#pragma unroll
            for (int p = 0; p < 4; p++) {
                uint32_t r4[4];
                ldsm_x4_t(r4, su + SV_OFF + (uint32_t)((kk + tr_r) * LQH
                                                       + p * 16 + tr_c) * 2);
                mma_f16(o[2 * p + 0], a, r4);
                mma_f16(o[2 * p + 1], a, r4 + 2);
            }
        }
        __syncthreads();   // protect sK/sV (and sP) before next iteration
    }

    // normalize + store fp16
    const float il0 = 1.0f / l0_;
    const float il1 = 1.0f / l1_;
    __half* yg = y + (size_t)b * SEQ * D_MODEL + (size_t)h * HDIM;
#pragma unroll
    for (int nf = 0; nf < 8; nf++) {
        const int col = nf * 8 + t * 2;
        const int r0 = q0 + wm0 + g;
        __half2 o0;
        o0.x = __float2half_rn(o[nf][0] * il0);
        o0.y = __float2half_rn(o[nf][1] * il0);
        *(__half2*)(yg + (size_t)r0 * D_MODEL + col) = o0;
        __half2 o1;
        o1.x = __float2half_rn(o[nf][2] * il1);
        o1.y = __float2half_rn(o[nf][3] * il1);
        *(__half2*)(yg + (size_t)(r0 + 8) * D_MODEL + col) = o1;
    }
}

// ===========================================================================
// launch
// ===========================================================================
extern "C" void kernel_launch(void* const* d_in, const int* in_sizes, int n_in,
                              void* d_out, int out_size) {
    const float* x   = (const float*)d_in[0];
    const float* Wk  = (const float*)d_in[1];
    const float* Wq  = (const float*)d_in[2];
    const float* Wv  = (const float*)d_in[3];
    const float* Wp  = (const float*)d_in[4];
    const float* bp  = (const float*)d_in[5];
    const float* g1  = (const float*)d_in[6];
    const float* b1  = (const float*)d_in[7];
    const float* g2  = (const float*)d_in[8];
    const float* b2  = (const float*)d_in[9];
    const float* W1  = (const float*)d_in[10];
    const float* bm1 = (const float*)d_in[11];
    const float* W2  = (const float*)d_in[12];
    const float* bm2 = (const float*)d_in[13];
    float* out = (float*)d_out;

    float* S = nullptr;
    cudaGetSymbolAddress((void**)&S, g_scratch);
    float*  xn    = S + 0 * CH;
    __half* xnh   = (__half*)(S + 1 * CH);
    __half* qkv   = (__half*)(S + 2 * CH);            // 12M halves (chunks 2-3)
    __half* yb    = (__half*)(S + 4 * CH);
    float*  hb    = S + 5 * CH;
    __half* hn    = (__half*)(S + 6 * CH);
    __half* m1    = (__half*)(S + 7 * CH);            // 16M halves (chunks 7-8)
    __half* WqkvH = (__half*)(S + 9 * CH);            // [1024,3072] halves
    __half* WpH   = (__half*)(S + 10 * CH);           // [1024,1024]
    __half* W1H   = (__half*)(S + 11 * CH);           // [1024,4096]
    __half* W2H   = (__half*)(S + 12 * CH);           // [4096,1024]

    cudaFuncSetAttribute(attn_kernel, cudaFuncAttributeMaxDynamicSharedMemorySize,
                         ATT_SMEM);
    cudaFuncSetAttribute(tgemm<false>, cudaFuncAttributeMaxDynamicSharedMemorySize,
                         GEMM_SMEM);
    cudaFuncSetAttribute(tgemm<true>, cudaFuncAttributeMaxDynamicSharedMemorySize,
                         GEMM_SMEM);

    // weight converts (layout preserved: [K,N])
    convert_pack_qkv<<<(D_MODEL * QKVN) / 1024, 256>>>(Wq, Wk, Wv, WqkvH);
    convert_kernel<<<(D_MODEL * D_MODEL) / 1024, 256>>>(Wp, WpH, D_MODEL * D_MODEL);
    convert_kernel<<<(D_MODEL * DFF) / 1024, 256>>>(W1, W1H, D_MODEL * DFF);
    convert_kernel<<<(DFF * D_MODEL) / 1024, 256>>>(W2, W2H, DFF * D_MODEL);

    ln_kernel<<<MROWS, 256>>>(x, g1, b1, xn, xnh);

    dim3 gqkv(QKVN / 128, MROWS / 128);
    tgemm<false><<<gqkv, 256, GEMM_SMEM>>>(xnh, WqkvH, nullptr, qkv,
                                           MROWS, QKVN, D_MODEL, nullptr, nullptr);

    dim3 ag(BATCH * NHEAD, SEQ / 64);
    attn_kernel<<<ag, 128, ATT_SMEM>>>(qkv, yb);

    dim3 g1024(D_MODEL / 128, MROWS / 128);
    tgemm<false><<<g1024, 256, GEMM_SMEM>>>(yb, WpH, hb, nullptr,
                                            MROWS, D_MODEL, D_MODEL, bp, xn);

    ln_kernel<<<MROWS, 256>>>(hb, g2, b2, nullptr, hn);

    dim3 g4096(DFF / 128, MROWS / 128);
    tgemm<true><<<g4096, 256, GEMM_SMEM>>>(hn, W1H, nullptr, m1,
                                           MROWS, DFF, D_MODEL, bm1, nullptr);

    tgemm<false><<<g1024, 256, GEMM_SMEM>>>(m1, W2H, out, nullptr,
                                            MROWS, D_MODEL, DFF, bm2, hb);

    (void)in_sizes; (void)n_in; (void)out_size;
}